// round 7
// baseline (speedup 1.0000x reference)
#include <cuda_runtime.h>
#include <cuda_bf16.h>
#include <cstdint>

// FrozenBNBEmbedding: fused blockwise-dequant + embedding gather.
// BLOCK (4096) == DIM (4096) => block id of any element of row r is r:
//   out[row, d] = code[ weight[token, d] ] * absmax[token]
//
// R6: winning R3/R5 shape (grid=8192, 1 row/CTA, 256 thr, 4 front-batched
// LDG.128, .cs streaming stores) + L2 policy split:
//   reads : createpolicy.fractional.L2::evict_last -> gathered row set
//           (~123MB unique) stays resident in the 126MB L2, so duplicate
//           tokens (~8%) and re-referenced sectors hit L2 instead of DRAM.
//   writes: st.global.cs (evict-first) -> 134MB write stream passes through
//           without evicting the read set.
//
// Inputs (metadata order):
//   d_in[0] = input  : int32 [4, 2048]      token ids (8192 rows)
//   d_in[1] = weight : int32 [50400, 4096]  int8 codes stored as int32
//   d_in[2] = absmax : fp32  [50400]        per-block scale (block == row)
//   d_in[3] = code   : fp32  [256]          dequant LUT
// Output: fp32 [4, 2048, 4096]

#define DIM 4096
#define VEC (DIM / 4)            // 1024 int4/float4 per row
#define NTHREADS 256
#define ITER (VEC / NTHREADS)    // 4

__device__ __forceinline__ void stg_cs_v4(float4* p, float4 v) {
    asm volatile("st.global.cs.v4.f32 [%0], {%1, %2, %3, %4};"
                 :: "l"(p), "f"(v.x), "f"(v.y), "f"(v.z), "f"(v.w));
}

__device__ __forceinline__ int4 ldg_evict_last_v4(const int4* p, uint64_t policy) {
    int4 q;
    asm volatile("ld.global.nc.L2::cache_hint.v4.u32 {%0, %1, %2, %3}, [%4], %5;"
                 : "=r"(q.x), "=r"(q.y), "=r"(q.z), "=r"(q.w)
                 : "l"(p), "l"(policy));
    return q;
}

__global__ __launch_bounds__(NTHREADS, 8)
void bnb_embed_kernel(const int* __restrict__ tokens,
                      const int* __restrict__ weight,
                      const float* __restrict__ absmax,
                      const float* __restrict__ code,
                      float* __restrict__ out)
{
    __shared__ float s_code[256];
    const int t = threadIdx.x;
    if (t < 256) s_code[t] = code[t];
    __syncthreads();

    // L2 evict-last policy for the weight-row reads.
    uint64_t policy;
    asm volatile("createpolicy.fractional.L2::evict_last.b64 %0, 1.0;"
                 : "=l"(policy));

    const int row = blockIdx.x;
    const int token = __ldg(&tokens[row]);
    const float amax = __ldg(&absmax[token]);

    const int4* __restrict__ src = reinterpret_cast<const int4*>(weight) +
                                   (size_t)token * VEC;
    float4* __restrict__ dst = reinterpret_cast<float4*>(out) +
                               (size_t)row * VEC;

    // Front-batch all 4 LDG.128 before any dependent work / stores.
    int4 q[ITER];
    #pragma unroll
    for (int k = 0; k < ITER; k++)
        q[k] = ldg_evict_last_v4(src + t + k * NTHREADS, policy);

    #pragma unroll
    for (int k = 0; k < ITER; k++) {
        float4 v;
        v.x = s_code[q[k].x & 0xFF] * amax;
        v.y = s_code[q[k].y & 0xFF] * amax;
        v.z = s_code[q[k].z & 0xFF] * amax;
        v.w = s_code[q[k].w & 0xFF] * amax;
        stg_cs_v4(dst + t + k * NTHREADS, v);
    }
}

extern "C" void kernel_launch(void* const* d_in, const int* in_sizes, int n_in,
                              void* d_out, int out_size)
{
    const int*   tokens = (const int*)d_in[0];
    const int*   weight = (const int*)d_in[1];
    const float* absmax = (const float*)d_in[2];
    const float* code   = (const float*)d_in[3];
    float*       out    = (float*)d_out;

    int n_rows = in_sizes[0];  // 8192
    bnb_embed_kernel<<<n_rows, NTHREADS>>>(tokens, weight, absmax, code, out);
}